// round 3
// baseline (speedup 1.0000x reference)
#include <cuda_runtime.h>
#include <cstdint>

#define N_TOK   131072
#define DIM     64
#define NE      1024
#define DECAYF  0.99f
#define ONE_M_D 0.01f
#define EPSF    1e-5f

// ---- output layout (reference return order, flattened, float32) ----
#define O_Q     0                       // quantize_st: N_TOK*DIM
#define O_DIFF  (O_Q + N_TOK*DIM)       // scalar
#define O_IND   (O_DIFF + 1)            // N_TOK
#define O_NEMB  (O_IND + N_TOK)         // DIM*NE
#define O_NCS   (O_NEMB + DIM*NE)       // NE
#define O_NEA   (O_NCS + NE)            // DIM*NE

// ---- scratch (no allocations allowed -> device globals) ----
__device__ float  g_enorm[NE];
__device__ float  g_embedT[NE*DIM];     // row j = codeword j (contiguous 64 floats)
__device__ float  g_count[NE];
__device__ float  g_embed_sum[DIM*NE];
__device__ double g_diff_acc;
__device__ float  g_n;

typedef unsigned long long ull;

// ---- f32x2 packed helpers (sm_103a) ----
__device__ __forceinline__ ull pack2(float v) {
    ull r;
    asm("mov.b64 %0, {%1, %1};" : "=l"(r) : "f"(v));
    return r;
}
__device__ __forceinline__ void fma2(ull& d, ull a, ull b) {
    asm("fma.rn.f32x2 %0, %1, %2, %0;" : "+l"(d) : "l"(a), "l"(b));
}
__device__ __forceinline__ void unpack2(ull v, float& lo, float& hi) {
    asm("mov.b64 {%0, %1}, %2;" : "=f"(lo), "=f"(hi) : "l"(v));
}

// =====================================================================
// K0a: transpose codebook, zero scratch   (grid 64 x 256)
// =====================================================================
__global__ void vq_prep_a(const float* __restrict__ embed) {
    int gid = blockIdx.x * blockDim.x + threadIdx.x;   // 0..16383 (float4 units)
    float4 v = ((const float4*)embed)[gid];
    int idx = gid * 4;
    int d = idx >> 10;
    int j = idx & 1023;
    g_embedT[(j + 0) * DIM + d] = v.x;
    g_embedT[(j + 1) * DIM + d] = v.y;
    g_embedT[(j + 2) * DIM + d] = v.z;
    g_embedT[(j + 3) * DIM + d] = v.w;
    ((float4*)g_embed_sum)[gid] = make_float4(0.f, 0.f, 0.f, 0.f);
    if (gid < NE) g_count[gid] = 0.f;
    if (gid == 0) g_diff_acc = 0.0;
}

// =====================================================================
// K0b: ||e_j||^2, warp per codeword   (grid 128 x 256)
// =====================================================================
__global__ void vq_prep_b() {
    int t = blockIdx.x * blockDim.x + threadIdx.x;
    int w = t >> 5;           // codeword
    int lane = t & 31;
    float2 v = *(const float2*)(g_embedT + w * DIM + lane * 2);
    float s = v.x * v.x + v.y * v.y;
    #pragma unroll
    for (int off = 16; off > 0; off >>= 1)
        s += __shfl_xor_sync(0xFFFFFFFFu, s, off);
    if (lane == 0) g_enorm[w] = s;
}

// =====================================================================
// K1: distance GEMM + argmin + quantize + diff + segment atomics
//   block: 256 thr, 128 tokens x 128-code chunks (x8), K=64 in smem
//   xs2: duplicated-f32x2 x tile [k][m], col-swizzled, stride 160
//   es : codebook chunk [k][j], stride 128
//   micro-tile 8 rows x 8 cols (4 col-pairs, interleaved jg+16u)
// =====================================================================
#define XS2_STRIDE 160
#define SMEM_BYTES (64*XS2_STRIDE*8 + 64*128*4)

__global__ void __launch_bounds__(256, 2) vq_main(const float* __restrict__ x,
                                                  const float* __restrict__ embed,
                                                  float* __restrict__ out) {
    extern __shared__ char smraw[];
    ull*   xs2 = (ull*)smraw;                         // [64][160] (cols 0..157 used)
    float* es  = (float*)(smraw + 64 * XS2_STRIDE * 8); // [64][128]

    const int tid = threadIdx.x;
    const int bm  = blockIdx.x * 128;
    const int jg  = tid & 15;
    const int mg  = tid >> 4;

    // ---- load x tile, duplicated + transposed: xs2[k][m + 2*(k>>2)] = {x,x} ----
    #pragma unroll
    for (int p = 0; p < 8; ++p) {
        int f  = tid + p * 256;        // 2048 float4s
        int m  = f >> 4;
        int k4 = f & 15;
        float4 v = *(const float4*)(x + (size_t)(bm + m) * DIM + k4 * 4);
        int col = m + 2 * k4;          // swizzle: 2-way max on store, bcast on load
        ull* base = xs2 + (size_t)(k4 * 4) * XS2_STRIDE + col;
        base[0 * XS2_STRIDE] = pack2(v.x);
        base[1 * XS2_STRIDE] = pack2(v.y);
        base[2 * XS2_STRIDE] = pack2(v.z);
        base[3 * XS2_STRIDE] = pack2(v.w);
    }

    float rmin[8];
    int   ridx[8];
    #pragma unroll
    for (int i = 0; i < 8; ++i) { rmin[i] = 3.402823466e+38f; ridx[i] = 0; }

    for (int c = 0; c < 8; ++c) {
        __syncthreads();
        // ---- codebook chunk es[k][j] (straight coalesced copy) ----
        #pragma unroll
        for (int p = 0; p < 8; ++p) {
            int f  = tid + p * 256;
            int k  = f >> 5;
            int c4 = f & 31;
            *(float4*)(es + k * 128 + c4 * 4) =
                *(const float4*)(embed + (size_t)k * NE + c * 128 + c4 * 4);
        }
        __syncthreads();

        ull acc[8][4];
        #pragma unroll
        for (int i = 0; i < 8; ++i)
            #pragma unroll
            for (int u = 0; u < 4; ++u) acc[i][u] = 0ULL;

        #pragma unroll 16
        for (int k = 0; k < 64; ++k) {
            const ull* xrow = xs2 + (size_t)k * XS2_STRIDE + mg * 8 + 2 * (k >> 2);
            ulonglong2 a01 = *(const ulonglong2*)(xrow + 0);
            ulonglong2 a23 = *(const ulonglong2*)(xrow + 2);
            ulonglong2 a45 = *(const ulonglong2*)(xrow + 4);
            ulonglong2 a67 = *(const ulonglong2*)(xrow + 6);
            ull a[8] = {a01.x, a01.y, a23.x, a23.y, a45.x, a45.y, a67.x, a67.y};
            const float* erow = es + k * 128 + 2 * jg;
            ull b[4];
            #pragma unroll
            for (int u = 0; u < 4; ++u)
                b[u] = *(const ull*)(erow + 32 * u);   // cols 2*(jg+16u), conflict-free
            #pragma unroll
            for (int i = 0; i < 8; ++i)
                #pragma unroll
                for (int u = 0; u < 4; ++u)
                    fma2(acc[i][u], a[i], b[u]);
        }

        // ---- dist = enorm - 2*dot, running argmin ----
        float2 en2[4];
        #pragma unroll
        for (int u = 0; u < 4; ++u)
            en2[u] = *(const float2*)(g_enorm + c * 128 + 2 * (jg + 16 * u));

        #pragma unroll
        for (int i = 0; i < 8; ++i) {
            #pragma unroll
            for (int u = 0; u < 4; ++u) {
                float lo, hi;
                unpack2(acc[i][u], lo, hi);
                int j0 = c * 128 + 2 * (jg + 16 * u);
                float d0 = fmaf(-2.f, lo, en2[u].x);
                float d1 = fmaf(-2.f, hi, en2[u].y);
                if (d0 < rmin[i]) { rmin[i] = d0; ridx[i] = j0; }
                if (d1 < rmin[i]) { rmin[i] = d1; ridx[i] = j0 + 1; }
            }
        }
    }

    // ---- cross-thread argmin reduction (reuse es region) ----
    __syncthreads();
    float* rmin_s = es;                         // [128][16]
    int*   ridx_s = (int*)(es + 128 * 16);      // [128][16]
    #pragma unroll
    for (int i = 0; i < 8; ++i) {
        int r = mg * 8 + i;
        rmin_s[r * 16 + jg] = rmin[i];
        ridx_s[r * 16 + jg] = ridx[i];
    }
    __syncthreads();

    __shared__ int s_ind[128];
    if (tid < 128) {
        float bv = rmin_s[tid * 16];
        int   bi = ridx_s[tid * 16];
        #pragma unroll
        for (int t = 1; t < 16; ++t) {
            float v  = rmin_s[tid * 16 + t];
            int   ix = ridx_s[tid * 16 + t];
            if (v < bv || (v == bv && ix < bi)) { bv = v; bi = ix; }
        }
        s_ind[tid] = bi;
        out[O_IND + bm + tid] = (float)bi;
        atomicAdd(&g_count[bi], 1.0f);
    }
    __syncthreads();

    // ---- epilogue: 2 threads per token (32 dims each) ----
    const int tk   = tid >> 1;
    const int half = tid & 1;
    const int ind  = s_ind[tk];
    const int token = bm + tk;
    const float* qrow = g_embedT + (size_t)ind * DIM + half * 32;
    float dsum = 0.f;
    #pragma unroll
    for (int uu = 0; uu < 32; uu += 4) {
        float4 q = *(const float4*)(qrow + uu);
        int kb = half * 32 + uu;
        float xv[4];
        #pragma unroll
        for (int s = 0; s < 4; ++s) {
            int k = kb + s;
            xv[s] = *(const float*)(xs2 + (size_t)k * XS2_STRIDE + tk + 2 * (k >> 2));
        }
        float e0 = q.x - xv[0], e1 = q.y - xv[1], e2 = q.z - xv[2], e3 = q.w - xv[3];
        dsum += e0*e0 + e1*e1 + e2*e2 + e3*e3;
        *(float4*)(out + O_Q + (size_t)token * DIM + kb) = q;
        atomicAdd(&g_embed_sum[(kb + 0) * NE + ind], xv[0]);
        atomicAdd(&g_embed_sum[(kb + 1) * NE + ind], xv[1]);
        atomicAdd(&g_embed_sum[(kb + 2) * NE + ind], xv[2]);
        atomicAdd(&g_embed_sum[(kb + 3) * NE + ind], xv[3]);
    }

    // ---- block-reduce diff, one double atomic per block ----
    #pragma unroll
    for (int off = 16; off > 0; off >>= 1)
        dsum += __shfl_xor_sync(0xFFFFFFFFu, dsum, off);
    __shared__ float s_red[8];
    if ((tid & 31) == 0) s_red[tid >> 5] = dsum;
    __syncthreads();
    if (tid == 0) {
        float t = 0.f;
        #pragma unroll
        for (int w = 0; w < 8; ++w) t += s_red[w];
        atomicAdd(&g_diff_acc, (double)t);
    }
}

// =====================================================================
// K2a: cluster-size EMA + n reduction (1 block, 1024 thr)
// =====================================================================
__global__ void vq_fin_a(const float* __restrict__ cluster_size,
                         float* __restrict__ out) {
    __shared__ float sr[NE];
    int j = threadIdx.x;
    float ncs = cluster_size[j] * DECAYF + ONE_M_D * g_count[j];
    out[O_NCS + j] = ncs;
    sr[j] = ncs;
    __syncthreads();
    for (int s = 512; s > 0; s >>= 1) {
        if (j < s) sr[j] += sr[j + s];
        __syncthreads();
    }
    if (j == 0) {
        g_n = sr[0];
        out[O_DIFF] = (float)(g_diff_acc * (1.0 / (double)((size_t)N_TOK * DIM)));
    }
}

// =====================================================================
// K2b: embed-avg EMA + normalized embed (grid 64 x 256)
// =====================================================================
__global__ void vq_fin_b(const float* __restrict__ embed_avg,
                         float* __restrict__ out) {
    int gid = blockIdx.x * blockDim.x + threadIdx.x;   // float4 units
    int idx = gid * 4;
    int j = idx & 1023;
    float4 ea = ((const float4*)embed_avg)[gid];
    float4 esum = ((const float4*)g_embed_sum)[gid];
    float4 nea;
    nea.x = ea.x * DECAYF + ONE_M_D * esum.x;
    nea.y = ea.y * DECAYF + ONE_M_D * esum.y;
    nea.z = ea.z * DECAYF + ONE_M_D * esum.z;
    nea.w = ea.w * DECAYF + ONE_M_D * esum.w;
    float n = g_n;
    float denom = n + (float)NE * EPSF;
    float c0 = (out[O_NCS + j + 0] + EPSF) / denom * n;
    float c1 = (out[O_NCS + j + 1] + EPSF) / denom * n;
    float c2 = (out[O_NCS + j + 2] + EPSF) / denom * n;
    float c3 = (out[O_NCS + j + 3] + EPSF) / denom * n;
    // NEA / NEMB regions are not 16B-aligned (odd base offset) -> scalar stores
    out[O_NEA + idx + 0] = nea.x;
    out[O_NEA + idx + 1] = nea.y;
    out[O_NEA + idx + 2] = nea.z;
    out[O_NEA + idx + 3] = nea.w;
    out[O_NEMB + idx + 0] = nea.x / c0;
    out[O_NEMB + idx + 1] = nea.y / c1;
    out[O_NEMB + idx + 2] = nea.z / c2;
    out[O_NEMB + idx + 3] = nea.w / c3;
}

extern "C" void kernel_launch(void* const* d_in, const int* in_sizes, int n_in,
                              void* d_out, int out_size) {
    const float* x            = (const float*)d_in[0];
    const float* embed        = (const float*)d_in[1];
    const float* cluster_size = (const float*)d_in[2];
    const float* embed_avg    = (const float*)d_in[3];
    float* out = (float*)d_out;

    cudaFuncSetAttribute(vq_main, cudaFuncAttributeMaxDynamicSharedMemorySize,
                         SMEM_BYTES);

    vq_prep_a<<<64, 256>>>(embed);
    vq_prep_b<<<128, 256>>>();
    vq_main<<<N_TOK / 128, 256, SMEM_BYTES>>>(x, embed, out);
    vq_fin_a<<<1, NE>>>(cluster_size, out);
    vq_fin_b<<<64, 256>>>(embed_avg, out);
}